// round 10
// baseline (speedup 1.0000x reference)
#include <cuda_runtime.h>
#include <math.h>

#define BATCH 256
#define NV 27
#define DMODEL 256
#define NHEADS 8
#define HDIM 32
#define FFDIM 1024
#define NLAYERS 3
#define THREADS 512

#define LDR 260            // activation row pitch (floats)
#define WLD 264            // weight tile row pitch (floats)
#define STAGES 4
#define OFF_T 0
#define OFF_Q (32 * LDR)
#define OFF_K (2 * 32 * LDR)
#define OFF_V (3 * 32 * LDR)
#define OFF_W (4 * 32 * LDR)
#define SMEM_FLOATS (OFF_W + STAGES * 16 * WLD)
#define SMEM_BYTES (SMEM_FLOATS * 4 + 2 * 27 * 28)

__device__ int   g_mode;
__device__ float g_zero[DMODEL];   // zero-initialized device global

// ---------------- mask dtype sniffer ----------------------------------------
__global__ void detect_kernel(const unsigned char* __restrict__ km) {
    __shared__ int cnt1, cnt3f;
    if (threadIdx.x == 0) { cnt1 = 0; cnt3f = 0; }
    __syncthreads();
    int l1 = 0, l3 = 0;
    for (int i = threadIdx.x; i < (BATCH * NV) / 4; i += blockDim.x) {
        if (km[4 * i + 1] != 0) l1++;
        if (km[4 * i + 3] == 0x3F) l3++;
    }
    atomicAdd(&cnt1, l1);
    atomicAdd(&cnt3f, l3);
    __syncthreads();
    if (threadIdx.x == 0) {
        if (cnt1 > 0)       g_mode = 0;  // uint8 bool
        else if (cnt3f > 0) g_mode = 2;  // float32
        else                g_mode = 1;  // int32
    }
}

// ---------------- cp.async helpers -------------------------------------------
__device__ __forceinline__ void cp_async16(void* smem, const void* gmem) {
    unsigned s = (unsigned)__cvta_generic_to_shared(smem);
    asm volatile("cp.async.cg.shared.global [%0], [%1], 16;" :: "r"(s), "l"(gmem));
}
__device__ __forceinline__ void cp_commit() {
    asm volatile("cp.async.commit_group;");
}
template <int N>
__device__ __forceinline__ void cp_wait() {
    asm volatile("cp.async.wait_group %0;" :: "n"(N));
}

// ---------------- CTA-level GEMM: C[32x256] = A[32x256] @ B[256x256] ----------
// 16 warps; warp w owns N columns [16w, 16w+16). 4-stage cp.async weight ring,
// prefetch distance 3. C may alias A (epilogue-guard barrier).
// EPI: 0 = bias -> Cs ; 1 = Cs += acc + bias ; 2 = gelu(acc + bias) -> Cs
template <int EPI>
__device__ __noinline__ void cta_gemm(const float* __restrict__ Asm,
                                      const float* __restrict__ Bg, int ldB,
                                      const float* __restrict__ bias,
                                      float* __restrict__ Cs,
                                      float* __restrict__ wb) {
    int tid  = threadIdx.x;
    int lane = tid & 31;
    int warp = tid >> 5;          // 0..15
    int grp  = lane >> 2;
    int quad = lane & 3;
    int lr   = tid >> 5;          // weight load row 0..15
    int lc   = (tid & 31) * 4;    // weight load col base 0..124

    float c[2][2][4];
    #pragma unroll
    for (int mi = 0; mi < 2; mi++)
        #pragma unroll
        for (int ni = 0; ni < 2; ni++)
            #pragma unroll
            for (int r = 0; r < 4; r++) c[mi][ni][r] = 0.0f;

    auto issue = [&](int kt, int st) {
        const float* src = Bg + (size_t)(kt * 16 + lr) * ldB + lc;
        float* dst = wb + st * (16 * WLD) + lr * WLD + lc;
        cp_async16(dst, src);
        cp_async16(dst + 128, src + 128);
        cp_commit();
    };

    auto compute = [&](int kt, int st) {
        const float* W = wb + st * (16 * WLD);
        #pragma unroll
        for (int ks = 0; ks < 16; ks += 8) {
            unsigned af[2][4], bf[2][2];
            int kc = kt * 16 + ks + quad;
            #pragma unroll
            for (int mi = 0; mi < 2; mi++) {
                int m = mi * 16 + grp;
                af[mi][0] = __float_as_uint(Asm[m * LDR + kc]);
                af[mi][1] = __float_as_uint(Asm[(m + 8) * LDR + kc]);
                af[mi][2] = __float_as_uint(Asm[m * LDR + kc + 4]);
                af[mi][3] = __float_as_uint(Asm[(m + 8) * LDR + kc + 4]);
            }
            #pragma unroll
            for (int ni = 0; ni < 2; ni++) {
                int n = warp * 16 + ni * 8 + grp;
                bf[ni][0] = __float_as_uint(W[(ks + quad) * WLD + n]);
                bf[ni][1] = __float_as_uint(W[(ks + quad + 4) * WLD + n]);
            }
            #pragma unroll
            for (int mi = 0; mi < 2; mi++)
                #pragma unroll
                for (int ni = 0; ni < 2; ni++) {
                    asm volatile(
                        "mma.sync.aligned.m16n8k8.row.col.f32.tf32.tf32.f32 "
                        "{%0,%1,%2,%3}, {%4,%5,%6,%7}, {%8,%9}, {%0,%1,%2,%3};"
                        : "+f"(c[mi][ni][0]), "+f"(c[mi][ni][1]),
                          "+f"(c[mi][ni][2]), "+f"(c[mi][ni][3])
                        : "r"(af[mi][0]), "r"(af[mi][1]),
                          "r"(af[mi][2]), "r"(af[mi][3]),
                          "r"(bf[ni][0]), "r"(bf[ni][1]));
                }
        }
    };

    issue(0, 0);
    issue(1, 1);
    issue(2, 2);

    // main loop: prefetch distance 3 (tiles kt+1..kt+3 in flight during compute)
    for (int kt = 0; kt < 14; kt++) {
        cp_wait<2>();                 // tile kt fully arrived
        __syncthreads();              // all warps done reading tile kt-1's stage
        if (kt + 3 < 16) issue(kt + 3, (kt + 3) & 3);
        compute(kt, kt & 3);
    }
    cp_wait<1>(); __syncthreads(); compute(14, 2);
    cp_wait<0>(); __syncthreads(); compute(15, 3);

    __syncthreads();   // epilogue guard: all A-reads complete before C writes
    #pragma unroll
    for (int mi = 0; mi < 2; mi++) {
        #pragma unroll
        for (int ni = 0; ni < 2; ni++) {
            #pragma unroll
            for (int r = 0; r < 4; r++) {
                int row = mi * 16 + grp + ((r >= 2) ? 8 : 0);
                int col = warp * 16 + ni * 8 + quad * 2 + (r & 1);
                float v = c[mi][ni][r] + bias[col];
                int idx = row * LDR + col;
                if (EPI == 0)      Cs[idx] = v;
                else if (EPI == 1) Cs[idx] = Cs[idx] + v;
                else               Cs[idx] = 0.5f * v *
                                       (1.0f + erff(v * 0.70710678118654752f));
            }
        }
    }
    __syncthreads();
}

// ---------------- CTA layernorm: 32 rows, warp per row (16 warps) -------------
__device__ __forceinline__ void cta_ln(const float* __restrict__ x,
                                       const float* __restrict__ g,
                                       const float* __restrict__ bta,
                                       float* __restrict__ y) {
    int tid = threadIdx.x, warp = tid >> 5, lane = tid & 31;
    for (int r = warp; r < 32; r += 16) {
        const float* xr = x + r * LDR + lane * 8;
        float4 v0 = *(const float4*)&xr[0];
        float4 v1 = *(const float4*)&xr[4];
        float s  = v0.x + v0.y + v0.z + v0.w + v1.x + v1.y + v1.z + v1.w;
        float ss = v0.x*v0.x + v0.y*v0.y + v0.z*v0.z + v0.w*v0.w
                 + v1.x*v1.x + v1.y*v1.y + v1.z*v1.z + v1.w*v1.w;
        #pragma unroll
        for (int off = 16; off > 0; off >>= 1) {
            s  += __shfl_xor_sync(0xffffffffu, s,  off);
            ss += __shfl_xor_sync(0xffffffffu, ss, off);
        }
        float mu  = s * (1.0f / DMODEL);
        float var = ss * (1.0f / DMODEL) - mu * mu;
        float rs  = rsqrtf(var + 1e-5f);
        float* yr = y + r * LDR;
        #pragma unroll
        for (int j = 0; j < 8; j++) {
            int cc = lane * 8 + j;
            float xv = (j < 4) ? ((const float*)&v0)[j] : ((const float*)&v1)[j - 4];
            yr[cc] = (xv - mu) * rs * g[cc] + bta[cc];
        }
    }
}

// ---------------- CTA attention (first 8 warps), in-place output over qb ------
__device__ __noinline__ void cta_attn(float* __restrict__ qb,
                                      const float* __restrict__ kb,
                                      const float* __restrict__ vb,
                                      const unsigned char* __restrict__ msk,
                                      const unsigned char* __restrict__ nbrt) {
    int tid = threadIdx.x;
    if (tid >= 256) return;
    int h = tid >> 5;
    int r = tid & 31;
    const float scale = 0.17677669529663687f;  // 1/sqrt(32)

    float4 q4[8];
    if (r < NV) {
        #pragma unroll
        for (int i = 0; i < 8; i++)
            q4[i] = *(const float4*)&qb[r * LDR + h * HDIM + i * 4];
    }
    float s[NV];
    float mx = -1e30f;
    #pragma unroll
    for (int l = 0; l < NV; l++) {
        s[l] = -1e30f;
        if (r < NV && msk[r * 28 + l]) {
            int j = nbrt[r * 28 + l];
            const float* kr = &kb[j * LDR + h * HDIM];
            float acc = 0.0f;
            #pragma unroll
            for (int i = 0; i < 8; i++) {
                float4 k4 = *(const float4*)&kr[i * 4];
                acc += q4[i].x * k4.x + q4[i].y * k4.y
                     + q4[i].z * k4.z + q4[i].w * k4.w;
            }
            s[l] = acc * scale;
            mx = fmaxf(mx, s[l]);
        }
    }
    float sum = 0.0f;
    #pragma unroll
    for (int l = 0; l < NV; l++) {
        float w = (s[l] > -1e29f) ? expf(s[l] - mx) : 0.0f;
        s[l] = w;
        sum += w;
    }
    float inv = (sum > 0.0f) ? (1.0f / sum) : 0.0f;

    float4 f4[8];
    #pragma unroll
    for (int i = 0; i < 8; i++) f4[i] = make_float4(0.f, 0.f, 0.f, 0.f);
    #pragma unroll
    for (int l = 0; l < NV; l++) {
        if (s[l] > 0.0f) {
            int j = nbrt[r * 28 + l];
            const float* vr = &vb[j * LDR + h * HDIM];
            float w = s[l];
            #pragma unroll
            for (int i = 0; i < 8; i++) {
                float4 v4 = *(const float4*)&vr[i * 4];
                f4[i].x += w * v4.x; f4[i].y += w * v4.y;
                f4[i].z += w * v4.z; f4[i].w += w * v4.w;
            }
        }
    }
    // write output in place over this thread's own q slice (no cross-thread reads)
    #pragma unroll
    for (int i = 0; i < 8; i++) {
        float4 o = make_float4(f4[i].x * inv, f4[i].y * inv,
                               f4[i].z * inv, f4[i].w * inv);
        *(float4*)&qb[r * LDR + h * HDIM + i * 4] = o;
    }
}

// ---------------- the megakernel: one CTA per patch ---------------------------
__global__ void __launch_bounds__(THREADS, 1)
mega_kernel(const float* __restrict__ patch, const void* __restrict__ km_raw,
            const float* __restrict__ w_in, const float* __restrict__ b_in,
            const float* __restrict__ pos,
            const float* __restrict__ ln1_g, const float* __restrict__ ln1_b,
            const float* __restrict__ ln2_g, const float* __restrict__ ln2_b,
            const float* __restrict__ Wq, const float* __restrict__ bq,
            const float* __restrict__ Wk, const float* __restrict__ bk,
            const float* __restrict__ Wv, const float* __restrict__ bv,
            const float* __restrict__ Wo, const float* __restrict__ bo,
            const float* __restrict__ W1, const float* __restrict__ b1,
            const float* __restrict__ W2, const float* __restrict__ b2,
            const float* __restrict__ w_out, const float* __restrict__ b_out,
            float* __restrict__ out) {
    extern __shared__ float sm[];
    float* t  = sm + OFF_T;
    float* qb = sm + OFF_Q;
    float* kb = sm + OFF_K;
    float* vb = sm + OFF_V;
    float* wb = sm + OFF_W;
    unsigned char* msk  = (unsigned char*)(sm + SMEM_FLOATS);
    unsigned char* nbrt = msk + 27 * 28;

    int b   = blockIdx.x;
    int tid = threadIdx.x;

    // ---- embed: t[v][c] = patch*w_in + b_in + pos ; pad rows 27..31 = 0 ----
    for (int idx = tid; idx < 32 * DMODEL; idx += THREADS) {
        int r = idx >> 8, cc = idx & 255;
        t[r * LDR + cc] = (r < NV)
            ? patch[b * NV + r] * w_in[cc] + b_in[cc] + pos[r * DMODEL + cc]
            : 0.0f;
    }

    // ---- per-patch neighbor table + mask ----
    int mode = g_mode;
    for (int idx = tid; idx < NV * NV; idx += THREADS) {
        int r = idx / NV, l = idx % NV;
        int zc = r / 9, yc = (r / 3) % 3, xc = r % 3;
        int z = zc + l / 9 - 1, y = yc + (l / 3) % 3 - 1, x = xc + l % 3 - 1;
        bool in = ((unsigned)z < 3u) && ((unsigned)y < 3u) && ((unsigned)x < 3u);
        int j = in ? (z * 9 + y * 3 + x) : 0;
        bool kv = false;
        if (in) {
            int gi = b * NV + j;
            if (mode == 0)      kv = ((const unsigned char*)km_raw)[gi] != 0;
            else if (mode == 1) kv = ((const int*)km_raw)[gi] != 0;
            else                kv = ((const float*)km_raw)[gi] != 0.0f;
        }
        msk[r * 28 + l]  = kv ? 1 : 0;
        nbrt[r * 28 + l] = (unsigned char)j;
    }
    __syncthreads();

    for (int l = 0; l < NLAYERS; l++) {
        const float* wq = Wq + (size_t)l * DMODEL * DMODEL;
        const float* wk = Wk + (size_t)l * DMODEL * DMODEL;
        const float* wv = Wv + (size_t)l * DMODEL * DMODEL;
        const float* wo = Wo + (size_t)l * DMODEL * DMODEL;
        const float* w1 = W1 + (size_t)l * DMODEL * FFDIM;
        const float* w2 = W2 + (size_t)l * FFDIM * DMODEL;

        // LN1(t) -> qb ; Q = qb@Wq in place ; K/V from raw t
        cta_ln(t, ln1_g + l * DMODEL, ln1_b + l * DMODEL, qb);
        __syncthreads();
        cta_gemm<0>(qb, wq, DMODEL, bq + l * DMODEL, qb, wb);  // in place
        cta_gemm<0>(t,  wk, DMODEL, bk + l * DMODEL, kb, wb);
        cta_gemm<0>(t,  wv, DMODEL, bv + l * DMODEL, vb, wb);

        cta_attn(qb, kb, vb, msk, nbrt);   // output in place over qb
        __syncthreads();

        // t += qb @ Wo + bo
        cta_gemm<1>(qb, wo, DMODEL, bo + l * DMODEL, t, wb);

        // FFN: t += gelu(ln2(t) @ W1 + b1) @ W2 + b2, 4 N-chunks of 256
        cta_ln(t, ln2_g + l * DMODEL, ln2_b + l * DMODEL, qb);
        __syncthreads();
        for (int cch = 0; cch < 4; cch++) {
            cta_gemm<2>(qb, w1 + cch * 256, FFDIM,
                        b1 + l * FFDIM + cch * 256, kb, wb);
            cta_gemm<1>(kb, w2 + (size_t)(cch * 256) * DMODEL, DMODEL,
                        (cch == 0) ? (b2 + l * DMODEL) : g_zero, t, wb);
        }
    }

    // ---- readout: out[b] = t[13] . w_out + b_out ----
    float p = (tid < DMODEL) ? t[13 * LDR + tid] * w_out[tid] : 0.0f;
    #pragma unroll
    for (int off = 16; off > 0; off >>= 1)
        p += __shfl_xor_sync(0xffffffffu, p, off);
    if ((tid & 31) == 0 && tid < DMODEL) wb[tid >> 5] = p;
    __syncthreads();
    if (tid == 0) {
        float s = 0.0f;
        #pragma unroll
        for (int w = 0; w < 8; w++) s += wb[w];
        out[b] = s + b_out[0];
    }
}

// ---------------- driver -----------------------------------------------------
extern "C" void kernel_launch(void* const* d_in, const int* in_sizes, int n_in,
                              void* d_out, int out_size) {
    const float* patch   = (const float*)d_in[0];
    const void*  km      = d_in[1];
    const float* w_in    = (const float*)d_in[2];
    const float* b_in    = (const float*)d_in[3];
    const float* pos     = (const float*)d_in[4];
    const float* ln1_g   = (const float*)d_in[5];
    const float* ln1_b   = (const float*)d_in[6];
    const float* ln2_g   = (const float*)d_in[7];
    const float* ln2_b   = (const float*)d_in[8];
    const float* Wq      = (const float*)d_in[9];
    const float* bq      = (const float*)d_in[10];
    const float* Wk      = (const float*)d_in[11];
    const float* bk      = (const float*)d_in[12];
    const float* Wv      = (const float*)d_in[13];
    const float* bv      = (const float*)d_in[14];
    const float* Wo      = (const float*)d_in[15];
    const float* bo      = (const float*)d_in[16];
    const float* W1      = (const float*)d_in[17];
    const float* b1      = (const float*)d_in[18];
    const float* W2      = (const float*)d_in[19];
    const float* b2      = (const float*)d_in[20];
    const float* w_out   = (const float*)d_in[21];
    const float* b_out   = (const float*)d_in[22];
    float* out = (float*)d_out;

    static int configured = 0;
    if (!configured) {
        cudaFuncSetAttribute(mega_kernel,
                             cudaFuncAttributeMaxDynamicSharedMemorySize,
                             SMEM_BYTES);
        configured = 1;
    }

    detect_kernel<<<1, 256>>>((const unsigned char*)km);
    mega_kernel<<<BATCH, THREADS, SMEM_BYTES>>>(
        patch, km, w_in, b_in, pos,
        ln1_g, ln1_b, ln2_g, ln2_b,
        Wq, bq, Wk, bk, Wv, bv, Wo, bo,
        W1, b1, W2, b2, w_out, b_out, out);
}

// round 11
// speedup vs baseline: 1.0782x; 1.0782x over previous
#include <cuda_runtime.h>
#include <cuda_bf16.h>
#include <math.h>

#define BATCH 256
#define NV 27
#define DMODEL 256
#define FFDIM 1024
#define NLAYERS 3
#define THREADS 512

// pitches
#define TLDW 260           // fp32 activation pitch (words): 260 % 32 == 4 -> conflict-free A-frags
#define KLDE 258           // bf16 k/v pitch (elements): 129 words -> row-spread banks
#define HLDW 132           // fp32 h-chunk pitch (words): 132 % 32 == 4
// byte offsets in dynamic SMEM
#define B_T 0                         // t: 64 x 260 f32        = 66560
#define B_X 66560                     // x: 64 x 260 f32        = 66560
#define B_KV 133120                   // k: 54 x 258 bf16 (27864, padded 27872)
#define B_V (B_KV + 27872)            // v: same
#define B_RING (B_KV + 55744)         // ring: 2 x 16 x 264 f32 = 33792
#define B_MSK (B_RING + 33792)        // msk: 2 x 27 x 28 bytes = 1512
#define B_NBR (B_MSK + 1512)          // nbrt: 1512
#define SMEM_BYTES (B_NBR + 1512 + 32)

__device__ int   g_mode;
__device__ float g_zero[DMODEL];   // zero-initialized

// ---------------- mask dtype sniffer ----------------------------------------
__global__ void detect_kernel(const unsigned char* __restrict__ km) {
    __shared__ int cnt1, cnt3f;
    if (threadIdx.x == 0) { cnt1 = 0; cnt3f = 0; }
    __syncthreads();
    int l1 = 0, l3 = 0;
    for (int i = threadIdx.x; i < (BATCH * NV) / 4; i += blockDim.x) {
        if (km[4 * i + 1] != 0) l1++;
        if (km[4 * i + 3] == 0x3F) l3++;
    }
    atomicAdd(&cnt1, l1);
    atomicAdd(&cnt3f, l3);
    __syncthreads();
    if (threadIdx.x == 0) {
        if (cnt1 > 0)       g_mode = 0;
        else if (cnt3f > 0) g_mode = 2;
        else                g_mode = 1;
    }
}

// ---------------- cp.async helpers -------------------------------------------
__device__ __forceinline__ void cp_async16(void* smem, const void* gmem) {
    unsigned s = (unsigned)__cvta_generic_to_shared(smem);
    asm volatile("cp.async.cg.shared.global [%0], [%1], 16;" :: "r"(s), "l"(gmem));
}
__device__ __forceinline__ void cp_commit() {
    asm volatile("cp.async.commit_group;");
}
template <int N>
__device__ __forceinline__ void cp_wait() {
    asm volatile("cp.async.wait_group %0;" :: "n"(N));
}

// ---------------- CTA GEMM: C[64 x NCOLS] = A[64 x K] @ B[K x NCOLS] ----------
// 16 warps, warp w owns N cols [w*NCOLS/16, +NCOLS/16). 2-stage weight ring.
// EPI: 0 = bias->f32, 1 = f32 accumulate, 2 = gelu->f32, 3 = bf16 store (row<54)
template <int EPI, int NKT, int NCOLS, int ALDW, int CLDW>
__device__ __noinline__ void cta_gemm(const float* __restrict__ Asm,
                                      const float* __restrict__ Bg, int ldB,
                                      const float* __restrict__ bias,
                                      float* __restrict__ Cs,
                                      float* __restrict__ ring) {
    constexpr int WLDW = (NCOLS == 256) ? 264 : 136;
    constexpr int NSL  = NCOLS / 16;     // 16 or 8
    constexpr int NI   = NSL / 8;        // 2 or 1

    int tid  = threadIdx.x;
    int lane = tid & 31;
    int warp = tid >> 5;
    int grp  = lane >> 2;
    int quad = lane & 3;
    int lr   = tid >> 5;
    int lc   = (tid & 31) * ((NCOLS == 256) ? 8 : 4);

    float c[4][NI][4];
    #pragma unroll
    for (int mi = 0; mi < 4; mi++)
        #pragma unroll
        for (int ni = 0; ni < NI; ni++)
            #pragma unroll
            for (int r = 0; r < 4; r++) c[mi][ni][r] = 0.0f;

    auto issue = [&](int kt, int st) {
        const float* src = Bg + (size_t)(kt * 16 + lr) * ldB + lc;
        float* dst = ring + st * (16 * WLDW) + lr * WLDW + lc;
        cp_async16(dst, src);
        if (NCOLS == 256) cp_async16(dst + 4, src + 4);
        cp_commit();
    };

    issue(0, 0);
    for (int kt = 0; kt < NKT; kt++) {
        cp_wait<0>();
        __syncthreads();   // all warps done with the stage about to be refilled
        if (kt + 1 < NKT) issue(kt + 1, (kt + 1) & 1);

        const float* W = ring + (kt & 1) * (16 * WLDW);
        #pragma unroll
        for (int ks = 0; ks < 16; ks += 8) {
            int kc = kt * 16 + ks + quad;
            unsigned bf[NI][2];
            #pragma unroll
            for (int ni = 0; ni < NI; ni++) {
                int n = warp * NSL + ni * 8 + grp;
                bf[ni][0] = __float_as_uint(W[(ks + quad) * WLDW + n]);
                bf[ni][1] = __float_as_uint(W[(ks + quad + 4) * WLDW + n]);
            }
            #pragma unroll
            for (int mi = 0; mi < 4; mi++) {
                int m = mi * 16 + grp;
                unsigned a0 = __float_as_uint(Asm[m * ALDW + kc]);
                unsigned a1 = __float_as_uint(Asm[(m + 8) * ALDW + kc]);
                unsigned a2 = __float_as_uint(Asm[m * ALDW + kc + 4]);
                unsigned a3 = __float_as_uint(Asm[(m + 8) * ALDW + kc + 4]);
                #pragma unroll
                for (int ni = 0; ni < NI; ni++) {
                    asm volatile(
                        "mma.sync.aligned.m16n8k8.row.col.f32.tf32.tf32.f32 "
                        "{%0,%1,%2,%3}, {%4,%5,%6,%7}, {%8,%9}, {%0,%1,%2,%3};"
                        : "+f"(c[mi][ni][0]), "+f"(c[mi][ni][1]),
                          "+f"(c[mi][ni][2]), "+f"(c[mi][ni][3])
                        : "r"(a0), "r"(a1), "r"(a2), "r"(a3),
                          "r"(bf[ni][0]), "r"(bf[ni][1]));
                }
            }
        }
    }

    __syncthreads();   // guard: allows C to alias A (in-place Q)
    #pragma unroll
    for (int mi = 0; mi < 4; mi++) {
        #pragma unroll
        for (int ni = 0; ni < NI; ni++) {
            int colb = warp * NSL + ni * 8 + quad * 2;
            float v0 = c[mi][ni][0] + bias[colb];
            float v1 = c[mi][ni][1] + bias[colb + 1];
            float v2 = c[mi][ni][2] + bias[colb];
            float v3 = c[mi][ni][3] + bias[colb + 1];
            int r0 = mi * 16 + grp;
            int r1 = r0 + 8;
            if (EPI == 3) {
                __nv_bfloat16* cb = (__nv_bfloat16*)Cs;
                if (r0 < 54)
                    *(__nv_bfloat162*)(cb + r0 * KLDE + colb) =
                        __floats2bfloat162_rn(v0, v1);
                if (r1 < 54)
                    *(__nv_bfloat162*)(cb + r1 * KLDE + colb) =
                        __floats2bfloat162_rn(v2, v3);
            } else {
                int i0 = r0 * CLDW + colb;
                int i1 = r1 * CLDW + colb;
                if (EPI == 0) {
                    Cs[i0] = v0; Cs[i0 + 1] = v1;
                    Cs[i1] = v2; Cs[i1 + 1] = v3;
                } else if (EPI == 1) {
                    Cs[i0] += v0; Cs[i0 + 1] += v1;
                    Cs[i1] += v2; Cs[i1 + 1] += v3;
                } else {
                    const float is2 = 0.70710678118654752f;
                    Cs[i0]     = 0.5f * v0 * (1.0f + erff(v0 * is2));
                    Cs[i0 + 1] = 0.5f * v1 * (1.0f + erff(v1 * is2));
                    Cs[i1]     = 0.5f * v2 * (1.0f + erff(v2 * is2));
                    Cs[i1 + 1] = 0.5f * v3 * (1.0f + erff(v3 * is2));
                }
            }
        }
    }
    __syncthreads();
}

// ---------------- CTA layernorm: 64 rows, 16 warps ----------------------------
__device__ __forceinline__ void cta_ln(const float* __restrict__ x,
                                       const float* __restrict__ g,
                                       const float* __restrict__ bta,
                                       float* __restrict__ y) {
    int tid = threadIdx.x, warp = tid >> 5, lane = tid & 31;
    #pragma unroll
    for (int it = 0; it < 4; it++) {
        int r = warp + it * 16;
        const float* xr = x + r * TLDW + lane * 8;
        float4 v0 = *(const float4*)&xr[0];
        float4 v1 = *(const float4*)&xr[4];
        float s  = v0.x + v0.y + v0.z + v0.w + v1.x + v1.y + v1.z + v1.w;
        float ss = v0.x*v0.x + v0.y*v0.y + v0.z*v0.z + v0.w*v0.w
                 + v1.x*v1.x + v1.y*v1.y + v1.z*v1.z + v1.w*v1.w;
        #pragma unroll
        for (int off = 16; off > 0; off >>= 1) {
            s  += __shfl_xor_sync(0xffffffffu, s,  off);
            ss += __shfl_xor_sync(0xffffffffu, ss, off);
        }
        float mu  = s * (1.0f / DMODEL);
        float var = ss * (1.0f / DMODEL) - mu * mu;
        float rs  = rsqrtf(var + 1e-5f);
        float* yr = y + r * TLDW;
        #pragma unroll
        for (int j = 0; j < 8; j++) {
            int cc = lane * 8 + j;
            float xv = (j < 4) ? ((const float*)&v0)[j] : ((const float*)&v1)[j - 4];
            yr[cc] = (xv - mu) * rs * g[cc] + bta[cc];
        }
    }
}

// ---------------- attention: 16 warps = 2 patches x 8 heads -------------------
__device__ __noinline__ void cta_attn(float* __restrict__ x,
                                      const __nv_bfloat16* __restrict__ kb,
                                      const __nv_bfloat16* __restrict__ vb,
                                      const unsigned char* __restrict__ msk,
                                      const unsigned char* __restrict__ nbrt) {
    int tid  = threadIdx.x;
    int warp = tid >> 5;
    int p    = warp >> 3;          // patch 0/1
    int h    = warp & 7;           // head
    int r    = tid & 31;           // query voxel
    if (r >= NV) return;
    const float scale = 0.17677669529663687f;

    int row = 27 * p + r;
    float4 q4[8];
    #pragma unroll
    for (int i = 0; i < 8; i++)
        q4[i] = *(const float4*)&x[row * TLDW + h * 32 + i * 4];

    const unsigned char* mr = msk  + p * 756 + r * 28;
    const unsigned char* nr = nbrt + p * 756 + r * 28;

    float s[NV];
    float mx = -1e30f;
    #pragma unroll
    for (int l = 0; l < NV; l++) {
        s[l] = -1e30f;
        if (mr[l]) {
            int jr = 27 * p + nr[l];
            const __nv_bfloat162* kr =
                (const __nv_bfloat162*)(kb + jr * KLDE + h * 32);
            float acc = 0.0f;
            #pragma unroll
            for (int i = 0; i < 8; i++) {
                float2 a = __bfloat1622float2(kr[2 * i]);
                float2 b = __bfloat1622float2(kr[2 * i + 1]);
                const float* q = (const float*)&q4[i];
                acc += q[0] * a.x + q[1] * a.y + q[2] * b.x + q[3] * b.y;
            }
            s[l] = acc * scale;
            mx = fmaxf(mx, s[l]);
        }
    }
    float sum = 0.0f;
    #pragma unroll
    for (int l = 0; l < NV; l++) {
        float w = (s[l] > -1e29f) ? expf(s[l] - mx) : 0.0f;
        s[l] = w;
        sum += w;
    }
    float inv = (sum > 0.0f) ? (1.0f / sum) : 0.0f;

    float o[32];
    #pragma unroll
    for (int i = 0; i < 32; i++) o[i] = 0.0f;
    #pragma unroll
    for (int l = 0; l < NV; l++) {
        if (s[l] > 0.0f) {
            int jr = 27 * p + nr[l];
            const __nv_bfloat162* vr =
                (const __nv_bfloat162*)(vb + jr * KLDE + h * 32);
            float w = s[l];
            #pragma unroll
            for (int i = 0; i < 16; i++) {
                float2 vv = __bfloat1622float2(vr[i]);
                o[2 * i]     += w * vv.x;
                o[2 * i + 1] += w * vv.y;
            }
        }
    }
    #pragma unroll
    for (int i = 0; i < 32; i++)
        x[row * TLDW + h * 32 + i] = o[i] * inv;
}

// ---------------- megakernel: one CTA per 2 patches ---------------------------
__global__ void __launch_bounds__(THREADS, 1)
mega_kernel(const float* __restrict__ patch, const void* __restrict__ km_raw,
            const float* __restrict__ w_in, const float* __restrict__ b_in,
            const float* __restrict__ pos,
            const float* __restrict__ ln1_g, const float* __restrict__ ln1_b,
            const float* __restrict__ ln2_g, const float* __restrict__ ln2_b,
            const float* __restrict__ Wq, const float* __restrict__ bq,
            const float* __restrict__ Wk, const float* __restrict__ bk,
            const float* __restrict__ Wv, const float* __restrict__ bv,
            const float* __restrict__ Wo, const float* __restrict__ bo,
            const float* __restrict__ W1, const float* __restrict__ b1,
            const float* __restrict__ W2, const float* __restrict__ b2,
            const float* __restrict__ w_out, const float* __restrict__ b_out,
            float* __restrict__ out) {
    extern __shared__ char sm[];
    float* t    = (float*)(sm + B_T);
    float* x    = (float*)(sm + B_X);
    __nv_bfloat16* kb = (__nv_bfloat16*)(sm + B_KV);
    __nv_bfloat16* vb = (__nv_bfloat16*)(sm + B_V);
    float* hbuf = (float*)(sm + B_KV);      // overlays k/v after attention
    float* ring = (float*)(sm + B_RING);
    unsigned char* msk  = (unsigned char*)(sm + B_MSK);
    unsigned char* nbrt = (unsigned char*)(sm + B_NBR);

    int bb  = blockIdx.x;        // handles patches 2bb, 2bb+1
    int tid = threadIdx.x;

    // ---- embed (packed rows 27p + r; rows 54-63 zero) ----
    for (int idx = tid; idx < 64 * DMODEL; idx += THREADS) {
        int row = idx >> 8, cc = idx & 255;
        float v = 0.0f;
        if (row < 54) {
            int p = (row >= 27), r = row - 27 * p;
            v = patch[(2 * bb + p) * NV + r] * w_in[cc] + b_in[cc]
              + pos[r * DMODEL + cc];
        }
        t[row * TLDW + cc] = v;
    }

    // ---- per-patch neighbor table + mask ----
    int mode = g_mode;
    for (int idx = tid; idx < 2 * NV * NV; idx += THREADS) {
        int p = idx / (NV * NV);
        int rem = idx - p * NV * NV;
        int r = rem / NV, l = rem % NV;
        int zc = r / 9, yc = (r / 3) % 3, xc = r % 3;
        int z = zc + l / 9 - 1, y = yc + (l / 3) % 3 - 1, xx = xc + l % 3 - 1;
        bool in = ((unsigned)z < 3u) && ((unsigned)y < 3u) && ((unsigned)xx < 3u);
        int j = in ? (z * 9 + y * 3 + xx) : 0;
        bool kv = false;
        if (in) {
            int gi = (2 * bb + p) * NV + j;
            if (mode == 0)      kv = ((const unsigned char*)km_raw)[gi] != 0;
            else if (mode == 1) kv = ((const int*)km_raw)[gi] != 0;
            else                kv = ((const float*)km_raw)[gi] != 0.0f;
        }
        msk[p * 756 + r * 28 + l]  = kv ? 1 : 0;
        nbrt[p * 756 + r * 28 + l] = (unsigned char)j;
    }
    __syncthreads();

    for (int l = 0; l < NLAYERS; l++) {
        const float* wq = Wq + (size_t)l * DMODEL * DMODEL;
        const float* wk = Wk + (size_t)l * DMODEL * DMODEL;
        const float* wv = Wv + (size_t)l * DMODEL * DMODEL;
        const float* wo = Wo + (size_t)l * DMODEL * DMODEL;
        const float* w1 = W1 + (size_t)l * DMODEL * FFDIM;
        const float* w2 = W2 + (size_t)l * FFDIM * DMODEL;

        // LN1(t) -> x ; Q = x@Wq in place (fp32); K/V from t -> bf16
        cta_ln(t, ln1_g + l * DMODEL, ln1_b + l * DMODEL, x);
        cta_gemm<0, 16, 256, TLDW, TLDW>(x, wq, DMODEL, bq + l * DMODEL, x, ring);
        cta_gemm<3, 16, 256, TLDW, 0>(t, wk, DMODEL, bk + l * DMODEL,
                                      (float*)kb, ring);
        cta_gemm<3, 16, 256, TLDW, 0>(t, wv, DMODEL, bv + l * DMODEL,
                                      (float*)vb, ring);

        cta_attn(x, kb, vb, msk, nbrt);   // out in place over x
        __syncthreads();

        // t += x @ Wo + bo
        cta_gemm<1, 16, 256, TLDW, TLDW>(x, wo, DMODEL, bo + l * DMODEL, t, ring);

        // FFN in 8 chunks of 128: t += gelu(LN2(t)@W1c + b1c) @ W2c (+ b2 once)
        cta_ln(t, ln2_g + l * DMODEL, ln2_b + l * DMODEL, x);
        for (int cch = 0; cch < 8; cch++) {
            cta_gemm<2, 16, 128, TLDW, HLDW>(x, w1 + cch * 128, FFDIM,
                                             b1 + l * FFDIM + cch * 128,
                                             hbuf, ring);
            cta_gemm<1, 8, 256, HLDW, TLDW>(hbuf,
                                            w2 + (size_t)(cch * 128) * DMODEL,
                                            DMODEL,
                                            (cch == 0) ? (b2 + l * DMODEL)
                                                       : g_zero,
                                            t, ring);
        }
    }

    // ---- readout: out[2bb+p] = t[27p+13] . w_out + b_out ----
    {
        int p = tid >> 8, cc = tid & 255;
        float v = t[(27 * p + 13) * TLDW + cc] * w_out[cc];
        #pragma unroll
        for (int off = 16; off > 0; off >>= 1)
            v += __shfl_xor_sync(0xffffffffu, v, off);
        if ((tid & 31) == 0) ring[tid >> 5] = v;
        __syncthreads();
        if (tid == 0) {
            float s = 0.0f;
            #pragma unroll
            for (int w = 0; w < 8; w++) s += ring[w];
            out[2 * bb] = s + b_out[0];
        }
        if (tid == 256) {
            float s = 0.0f;
            #pragma unroll
            for (int w = 8; w < 16; w++) s += ring[w];
            out[2 * bb + 1] = s + b_out[0];
        }
    }
}

// ---------------- driver -----------------------------------------------------
extern "C" void kernel_launch(void* const* d_in, const int* in_sizes, int n_in,
                              void* d_out, int out_size) {
    const float* patch   = (const float*)d_in[0];
    const void*  km      = d_in[1];
    const float* w_in    = (const float*)d_in[2];
    const float* b_in    = (const float*)d_in[3];
    const float* pos     = (const float*)d_in[4];
    const float* ln1_g   = (const float*)d_in[5];
    const float* ln1_b   = (const float*)d_in[6];
    const float* ln2_g   = (const float*)d_in[7];
    const float* ln2_b   = (const float*)d_in[8];
    const float* Wq      = (const float*)d_in[9];
    const float* bq      = (const float*)d_in[10];
    const float* Wk      = (const float*)d_in[11];
    const float* bk      = (const float*)d_in[12];
    const float* Wv      = (const float*)d_in[13];
    const float* bv      = (const float*)d_in[14];
    const float* Wo      = (const float*)d_in[15];
    const float* bo      = (const float*)d_in[16];
    const float* W1      = (const float*)d_in[17];
    const float* b1      = (const float*)d_in[18];
    const float* W2      = (const float*)d_in[19];
    const float* b2      = (const float*)d_in[20];
    const float* w_out   = (const float*)d_in[21];
    const float* b_out   = (const float*)d_in[22];
    float* out = (float*)d_out;

    static int configured = 0;
    if (!configured) {
        cudaFuncSetAttribute(mega_kernel,
                             cudaFuncAttributeMaxDynamicSharedMemorySize,
                             SMEM_BYTES);
        configured = 1;
    }

    detect_kernel<<<1, 256>>>((const unsigned char*)km);
    mega_kernel<<<BATCH / 2, THREADS, SMEM_BYTES>>>(
        patch, km, w_in, b_in, pos,
        ln1_g, ln1_b, ln2_g, ln2_b,
        Wq, bq, Wk, bk, Wv, bv, Wo, bo,
        W1, b1, W2, b2, w_out, b_out, out);
}

// round 12
// speedup vs baseline: 1.0855x; 1.0067x over previous
#include <cuda_runtime.h>
#include <cuda_bf16.h>
#include <math.h>

#define BATCH 256
#define NV 27
#define DMODEL 256
#define FFDIM 1024
#define NLAYERS 3
#define THREADS 512

// pitches
#define TLDW 260           // fp32 activation pitch (words)
#define KLDE 258           // bf16 k/v pitch (elements)
#define HLDW 132           // fp32 h-chunk pitch (words)
// byte offsets in dynamic SMEM (54-row activation buffers)
#define B_T 0                          // t: 54 x 260 f32 = 56160
#define B_X 56160                      // x: 54 x 260 f32 = 56160
#define B_KV 112320                    // k: 54 x 258 bf16 (27864 -> 27872)
#define B_V (B_KV + 27872)             // v: same
#define B_RING (B_KV + 55744)          // ring: 3 x 16 x 264 f32 = 50688
#define B_MSK (B_RING + 50688)         // msk: 2 x 27 x 28 = 1512
#define B_NBR (B_MSK + 1512)
#define SMEM_BYTES (B_NBR + 1512 + 32)

__device__ int   g_mode;
__device__ float g_zero[DMODEL];   // zero-initialized

// ---------------- mask dtype sniffer ----------------------------------------
__global__ void detect_kernel(const unsigned char* __restrict__ km) {
    __shared__ int cnt1, cnt3f;
    if (threadIdx.x == 0) { cnt1 = 0; cnt3f = 0; }
    __syncthreads();
    int l1 = 0, l3 = 0;
    for (int i = threadIdx.x; i < (BATCH * NV) / 4; i += blockDim.x) {
        if (km[4 * i + 1] != 0) l1++;
        if (km[4 * i + 3] == 0x3F) l3++;
    }
    atomicAdd(&cnt1, l1);
    atomicAdd(&cnt3f, l3);
    __syncthreads();
    if (threadIdx.x == 0) {
        if (cnt1 > 0)       g_mode = 0;
        else if (cnt3f > 0) g_mode = 2;
        else                g_mode = 1;
    }
}

// ---------------- cp.async helpers -------------------------------------------
__device__ __forceinline__ void cp_async16(void* smem, const void* gmem) {
    unsigned s = (unsigned)__cvta_generic_to_shared(smem);
    asm volatile("cp.async.cg.shared.global [%0], [%1], 16;" :: "r"(s), "l"(gmem));
}
__device__ __forceinline__ void cp_commit() {
    asm volatile("cp.async.commit_group;");
}
template <int N>
__device__ __forceinline__ void cp_wait() {
    asm volatile("cp.async.wait_group %0;" :: "n"(N));
}

// ---------------- CTA GEMM: C[64 x NCOLS] = A[64 x K] @ B[K x NCOLS] ----------
// 16 warps, warp w owns N cols [w*NCOLS/16, +NCOLS/16). 3-stage ring, dist 2.
// Output rows >= 54 are discarded (guards); A rows 54..63 may read junk that
// flows only into those discarded rows.
// EPI: 0 = bias->f32, 1 = f32 accumulate, 2 = gelu->f32, 3 = bf16 store
template <int EPI, int NKT, int NCOLS, int ALDW, int CLDW>
__device__ __noinline__ void cta_gemm(const float* __restrict__ Asm,
                                      const float* __restrict__ Bg, int ldB,
                                      const float* __restrict__ bias,
                                      float* __restrict__ Cs,
                                      float* __restrict__ ring) {
    constexpr int WLDW = (NCOLS == 256) ? 264 : 136;
    constexpr int NSL  = NCOLS / 16;     // 16 or 8
    constexpr int NI   = NSL / 8;        // 2 or 1

    int tid  = threadIdx.x;
    int lane = tid & 31;
    int warp = tid >> 5;
    int grp  = lane >> 2;
    int quad = lane & 3;
    int lr   = tid >> 5;
    int lc   = (tid & 31) * ((NCOLS == 256) ? 8 : 4);

    float c[4][NI][4];
    #pragma unroll
    for (int mi = 0; mi < 4; mi++)
        #pragma unroll
        for (int ni = 0; ni < NI; ni++)
            #pragma unroll
            for (int r = 0; r < 4; r++) c[mi][ni][r] = 0.0f;

    auto issue = [&](int kt, int st) {
        const float* src = Bg + (size_t)(kt * 16 + lr) * ldB + lc;
        float* dst = ring + st * (16 * WLDW) + lr * WLDW + lc;
        cp_async16(dst, src);
        if (NCOLS == 256) cp_async16(dst + 4, src + 4);
        cp_commit();
    };

    issue(0, 0);
    if (NKT > 1) issue(1, 1);

    for (int kt = 0; kt < NKT; kt++) {
        if (kt + 1 < NKT) cp_wait<1>();
        else              cp_wait<0>();
        __syncthreads();   // all warps done reading the stage being refilled
        if (kt + 2 < NKT) issue(kt + 2, (kt + 2) % 3);

        const float* W = ring + (kt % 3) * (16 * WLDW);
        #pragma unroll
        for (int ks = 0; ks < 16; ks += 8) {
            int kc = kt * 16 + ks + quad;
            unsigned bf[NI][2];
            #pragma unroll
            for (int ni = 0; ni < NI; ni++) {
                int n = warp * NSL + ni * 8 + grp;
                bf[ni][0] = __float_as_uint(W[(ks + quad) * WLDW + n]);
                bf[ni][1] = __float_as_uint(W[(ks + quad + 4) * WLDW + n]);
            }
            #pragma unroll
            for (int mi = 0; mi < 4; mi++) {
                int m = mi * 16 + grp;
                unsigned a0 = __float_as_uint(Asm[m * ALDW + kc]);
                unsigned a1 = __float_as_uint(Asm[(m + 8) * ALDW + kc]);
                unsigned a2 = __float_as_uint(Asm[m * ALDW + kc + 4]);
                unsigned a3 = __float_as_uint(Asm[(m + 8) * ALDW + kc + 4]);
                #pragma unroll
                for (int ni = 0; ni < NI; ni++) {
                    asm volatile(
                        "mma.sync.aligned.m16n8k8.row.col.f32.tf32.tf32.f32 "
                        "{%0,%1,%2,%3}, {%4,%5,%6,%7}, {%8,%9}, {%0,%1,%2,%3};"
                        : "+f"(c[mi][ni][0]), "+f"(c[mi][ni][1]),
                          "+f"(c[mi][ni][2]), "+f"(c[mi][ni][3])
                        : "r"(a0), "r"(a1), "r"(a2), "r"(a3),
                          "r"(bf[ni][0]), "r"(bf[ni][1]));
                }
            }
        }
    }

    __syncthreads();   // guard: allows C to alias A (in-place Q)
    #pragma unroll
    for (int mi = 0; mi < 4; mi++) {
        #pragma unroll
        for (int ni = 0; ni < NI; ni++) {
            int colb = warp * NSL + ni * 8 + quad * 2;
            float v0 = c[mi][ni][0] + bias[colb];
            float v1 = c[mi][ni][1] + bias[colb + 1];
            float v2 = c[mi][ni][2] + bias[colb];
            float v3 = c[mi][ni][3] + bias[colb + 1];
            int r0 = mi * 16 + grp;
            int r1 = r0 + 8;
            if (EPI == 3) {
                __nv_bfloat16* cb = (__nv_bfloat16*)Cs;
                if (r0 < 54)
                    *(__nv_bfloat162*)(cb + r0 * KLDE + colb) =
                        __floats2bfloat162_rn(v0, v1);
                if (r1 < 54)
                    *(__nv_bfloat162*)(cb + r1 * KLDE + colb) =
                        __floats2bfloat162_rn(v2, v3);
            } else {
                const float is2 = 0.70710678118654752f;
                if (r0 < 54) {
                    int i0 = r0 * CLDW + colb;
                    if (EPI == 0)      { Cs[i0] = v0; Cs[i0 + 1] = v1; }
                    else if (EPI == 1) { Cs[i0] += v0; Cs[i0 + 1] += v1; }
                    else {
                        Cs[i0]     = 0.5f * v0 * (1.0f + erff(v0 * is2));
                        Cs[i0 + 1] = 0.5f * v1 * (1.0f + erff(v1 * is2));
                    }
                }
                if (r1 < 54) {
                    int i1 = r1 * CLDW + colb;
                    if (EPI == 0)      { Cs[i1] = v2; Cs[i1 + 1] = v3; }
                    else if (EPI == 1) { Cs[i1] += v2; Cs[i1 + 1] += v3; }
                    else {
                        Cs[i1]     = 0.5f * v2 * (1.0f + erff(v2 * is2));
                        Cs[i1 + 1] = 0.5f * v3 * (1.0f + erff(v3 * is2));
                    }
                }
            }
        }
    }
    __syncthreads();
}

// ---------------- CTA layernorm: 54 rows, 16 warps ----------------------------
__device__ __forceinline__ void cta_ln(const float* __restrict__ x,
                                       const float* __restrict__ g,
                                       const float* __restrict__ bta,
                                       float* __restrict__ y) {
    int tid = threadIdx.x, warp = tid >> 5, lane = tid & 31;
    #pragma unroll
    for (int it = 0; it < 4; it++) {
        int r = warp + it * 16;
        if (r >= 54) break;
        const float* xr = x + r * TLDW + lane * 8;
        float4 v0 = *(const float4*)&xr[0];
        float4 v1 = *(const float4*)&xr[4];
        float s  = v0.x + v0.y + v0.z + v0.w + v1.x + v1.y + v1.z + v1.w;
        float ss = v0.x*v0.x + v0.y*v0.y + v0.z*v0.z + v0.w*v0.w
                 + v1.x*v1.x + v1.y*v1.y + v1.z*v1.z + v1.w*v1.w;
        #pragma unroll
        for (int off = 16; off > 0; off >>= 1) {
            s  += __shfl_xor_sync(0xffffffffu, s,  off);
            ss += __shfl_xor_sync(0xffffffffu, ss, off);
        }
        float mu  = s * (1.0f / DMODEL);
        float var = ss * (1.0f / DMODEL) - mu * mu;
        float rs  = rsqrtf(var + 1e-5f);
        float* yr = y + r * TLDW;
        #pragma unroll
        for (int j = 0; j < 8; j++) {
            int cc = lane * 8 + j;
            float xv = (j < 4) ? ((const float*)&v0)[j] : ((const float*)&v1)[j - 4];
            yr[cc] = (xv - mu) * rs * g[cc] + bta[cc];
        }
    }
}

// ---------------- attention: 16 warps = 2 patches x 8 heads -------------------
__device__ __noinline__ void cta_attn(float* __restrict__ x,
                                      const __nv_bfloat16* __restrict__ kb,
                                      const __nv_bfloat16* __restrict__ vb,
                                      const unsigned char* __restrict__ msk,
                                      const unsigned char* __restrict__ nbrt) {
    int tid  = threadIdx.x;
    int warp = tid >> 5;
    int p    = warp >> 3;          // patch 0/1
    int h    = warp & 7;           // head
    int r    = tid & 31;           // query voxel
    if (r >= NV) return;
    const float scale = 0.17677669529663687f;

    int row = 27 * p + r;
    float4 q4[8];
    #pragma unroll
    for (int i = 0; i < 8; i++)
        q4[i] = *(const float4*)&x[row * TLDW + h * 32 + i * 4];

    const unsigned char* mr = msk  + p * 756 + r * 28;
    const unsigned char* nr = nbrt + p * 756 + r * 28;

    float s[NV];
    float mx = -1e30f;
    #pragma unroll
    for (int l = 0; l < NV; l++) {
        s[l] = -1e30f;
        if (mr[l]) {
            int jr = 27 * p + nr[l];
            const __nv_bfloat162* kr =
                (const __nv_bfloat162*)(kb + jr * KLDE + h * 32);
            float acc = 0.0f;
            #pragma unroll
            for (int i = 0; i < 8; i++) {
                float2 a = __bfloat1622float2(kr[2 * i]);
                float2 b = __bfloat1622float2(kr[2 * i + 1]);
                const float* q = (const float*)&q4[i];
                acc += q[0] * a.x + q[1] * a.y + q[2] * b.x + q[3] * b.y;
            }
            s[l] = acc * scale;
            mx = fmaxf(mx, s[l]);
        }
    }
    float sum = 0.0f;
    #pragma unroll
    for (int l = 0; l < NV; l++) {
        float w = (s[l] > -1e29f) ? expf(s[l] - mx) : 0.0f;
        s[l] = w;
        sum += w;
    }
    float inv = (sum > 0.0f) ? (1.0f / sum) : 0.0f;

    float o[32];
    #pragma unroll
    for (int i = 0; i < 32; i++) o[i] = 0.0f;
    #pragma unroll
    for (int l = 0; l < NV; l++) {
        if (s[l] > 0.0f) {
            int jr = 27 * p + nr[l];
            const __nv_bfloat162* vr =
                (const __nv_bfloat162*)(vb + jr * KLDE + h * 32);
            float w = s[l];
            #pragma unroll
            for (int i = 0; i < 16; i++) {
                float2 vv = __bfloat1622float2(vr[i]);
                o[2 * i]     += w * vv.x;
                o[2 * i + 1] += w * vv.y;
            }
        }
    }
    #pragma unroll
    for (int i = 0; i < 32; i++)
        x[row * TLDW + h * 32 + i] = o[i] * inv;
}

// ---------------- megakernel: one CTA per 2 patches ---------------------------
__global__ void __launch_bounds__(THREADS, 1)
mega_kernel(const float* __restrict__ patch, const void* __restrict__ km_raw,
            const float* __restrict__ w_in, const float* __restrict__ b_in,
            const float* __restrict__ pos,
            const float* __restrict__ ln1_g, const float* __restrict__ ln1_b,
            const float* __restrict__ ln2_g, const float* __restrict__ ln2_b,
            const float* __restrict__ Wq, const float* __restrict__ bq,
            const float* __restrict__ Wk, const float* __restrict__ bk,
            const float* __restrict__ Wv, const float* __restrict__ bv,
            const float* __restrict__ Wo, const float* __restrict__ bo,
            const float* __restrict__ W1, const float* __restrict__ b1,
            const float* __restrict__ W2, const float* __restrict__ b2,
            const float* __restrict__ w_out, const float* __restrict__ b_out,
            float* __restrict__ out) {
    extern __shared__ char sm[];
    float* t    = (float*)(sm + B_T);
    float* x    = (float*)(sm + B_X);
    __nv_bfloat16* kb = (__nv_bfloat16*)(sm + B_KV);
    __nv_bfloat16* vb = (__nv_bfloat16*)(sm + B_V);
    float* hbuf = (float*)(sm + B_KV);      // overlays k/v during FFN
    float* ring = (float*)(sm + B_RING);
    unsigned char* msk  = (unsigned char*)(sm + B_MSK);
    unsigned char* nbrt = (unsigned char*)(sm + B_NBR);

    int bb  = blockIdx.x;        // handles patches 2bb, 2bb+1
    int tid = threadIdx.x;

    // ---- embed (packed rows 27p + r; only 54 rows exist) ----
    for (int idx = tid; idx < 54 * DMODEL; idx += THREADS) {
        int row = idx / DMODEL, cc = idx - row * DMODEL;
        int p = (row >= 27), r = row - 27 * p;
        t[row * TLDW + cc] = patch[(2 * bb + p) * NV + r] * w_in[cc] + b_in[cc]
                           + pos[r * DMODEL + cc];
    }

    // ---- per-patch neighbor table + mask ----
    int mode = g_mode;
    for (int idx = tid; idx < 2 * NV * NV; idx += THREADS) {
        int p = idx / (NV * NV);
        int rem = idx - p * NV * NV;
        int r = rem / NV, l = rem % NV;
        int zc = r / 9, yc = (r / 3) % 3, xc = r % 3;
        int z = zc + l / 9 - 1, y = yc + (l / 3) % 3 - 1, xx = xc + l % 3 - 1;
        bool in = ((unsigned)z < 3u) && ((unsigned)y < 3u) && ((unsigned)xx < 3u);
        int j = in ? (z * 9 + y * 3 + xx) : 0;
        bool kv = false;
        if (in) {
            int gi = (2 * bb + p) * NV + j;
            if (mode == 0)      kv = ((const unsigned char*)km_raw)[gi] != 0;
            else if (mode == 1) kv = ((const int*)km_raw)[gi] != 0;
            else                kv = ((const float*)km_raw)[gi] != 0.0f;
        }
        msk[p * 756 + r * 28 + l]  = kv ? 1 : 0;
        nbrt[p * 756 + r * 28 + l] = (unsigned char)j;
    }
    __syncthreads();

    for (int l = 0; l < NLAYERS; l++) {
        const float* wq = Wq + (size_t)l * DMODEL * DMODEL;
        const float* wk = Wk + (size_t)l * DMODEL * DMODEL;
        const float* wv = Wv + (size_t)l * DMODEL * DMODEL;
        const float* wo = Wo + (size_t)l * DMODEL * DMODEL;
        const float* w1 = W1 + (size_t)l * DMODEL * FFDIM;
        const float* w2 = W2 + (size_t)l * FFDIM * DMODEL;

        // LN1(t) -> x ; Q = x@Wq in place (fp32); K/V from t -> bf16
        cta_ln(t, ln1_g + l * DMODEL, ln1_b + l * DMODEL, x);
        __syncthreads();
        cta_gemm<0, 16, 256, TLDW, TLDW>(x, wq, DMODEL, bq + l * DMODEL, x, ring);
        cta_gemm<3, 16, 256, TLDW, 0>(t, wk, DMODEL, bk + l * DMODEL,
                                      (float*)kb, ring);
        cta_gemm<3, 16, 256, TLDW, 0>(t, wv, DMODEL, bv + l * DMODEL,
                                      (float*)vb, ring);

        cta_attn(x, kb, vb, msk, nbrt);   // out in place over x
        __syncthreads();

        // t += x @ Wo + bo
        cta_gemm<1, 16, 256, TLDW, TLDW>(x, wo, DMODEL, bo + l * DMODEL, t, ring);

        // FFN in 8 chunks of 128: t += gelu(LN2(t)@W1c + b1c) @ W2c (+ b2 once)
        cta_ln(t, ln2_g + l * DMODEL, ln2_b + l * DMODEL, x);
        __syncthreads();
        for (int cch = 0; cch < 8; cch++) {
            cta_gemm<2, 16, 128, TLDW, HLDW>(x, w1 + cch * 128, FFDIM,
                                             b1 + l * FFDIM + cch * 128,
                                             hbuf, ring);
            cta_gemm<1, 8, 256, HLDW, TLDW>(hbuf,
                                            w2 + (size_t)(cch * 128) * DMODEL,
                                            DMODEL,
                                            (cch == 0) ? (b2 + l * DMODEL)
                                                       : g_zero,
                                            t, ring);
        }
    }

    // ---- readout: out[2bb+p] = t[27p+13] . w_out + b_out ----
    {
        int p = tid >> 8, cc = tid & 255;
        float v = t[(27 * p + 13) * TLDW + cc] * w_out[cc];
        #pragma unroll
        for (int off = 16; off > 0; off >>= 1)
            v += __shfl_xor_sync(0xffffffffu, v, off);
        if ((tid & 31) == 0) ring[tid >> 5] = v;
        __syncthreads();
        if (tid == 0) {
            float s = 0.0f;
            #pragma unroll
            for (int w = 0; w < 8; w++) s += ring[w];
            out[2 * bb] = s + b_out[0];
        }
        if (tid == 256) {
            float s = 0.0f;
            #pragma unroll
            for (int w = 8; w < 16; w++) s += ring[w];
            out[2 * bb + 1] = s + b_out[0];
        }
    }
}

// ---------------- driver -----------------------------------------------------
extern "C" void kernel_launch(void* const* d_in, const int* in_sizes, int n_in,
                              void* d_out, int out_size) {
    const float* patch   = (const float*)d_in[0];
    const void*  km      = d_in[1];
    const float* w_in    = (const float*)d_in[2];
    const float* b_in    = (const float*)d_in[3];
    const float* pos     = (const float*)d_in[4];
    const float* ln1_g   = (const float*)d_in[5];
    const float* ln1_b   = (const float*)d_in[6];
    const float* ln2_g   = (const float*)d_in[7];
    const float* ln2_b   = (const float*)d_in[8];
    const float* Wq      = (const float*)d_in[9];
    const float* bq      = (const float*)d_in[10];
    const float* Wk      = (const float*)d_in[11];
    const float* bk      = (const float*)d_in[12];
    const float* Wv      = (const float*)d_in[13];
    const float* bv      = (const float*)d_in[14];
    const float* Wo      = (const float*)d_in[15];
    const float* bo      = (const float*)d_in[16];
    const float* W1      = (const float*)d_in[17];
    const float* b1      = (const float*)d_in[18];
    const float* W2      = (const float*)d_in[19];
    const float* b2      = (const float*)d_in[20];
    const float* w_out   = (const float*)d_in[21];
    const float* b_out   = (const float*)d_in[22];
    float* out = (float*)d_out;

    static int configured = 0;
    if (!configured) {
        cudaFuncSetAttribute(mega_kernel,
                             cudaFuncAttributeMaxDynamicSharedMemorySize,
                             SMEM_BYTES);
        configured = 1;
    }

    detect_kernel<<<1, 256>>>((const unsigned char*)km);
    mega_kernel<<<BATCH / 2, THREADS, SMEM_BYTES>>>(
        patch, km, w_in, b_in, pos,
        ln1_g, ln1_b, ln2_g, ln2_b,
        Wq, bq, Wk, bk, Wv, bv, Wo, bo,
        W1, b1, W2, b2, w_out, b_out, out);
}